// round 15
// baseline (speedup 1.0000x reference)
#include <cuda_runtime.h>
#include <cuda_bf16.h>
#include <cuda_fp16.h>
#include <math.h>

#define SEQL 2048
#define NB 2
#define TT (NB*SEQL)   /* 4096 tokens total */
#define ED 1024

#define LAMBDA_INIT 0.7836057665315f
/* QK_SCALE * log2(e) : scores computed directly in log2 domain */
#define QSCL 0.25503482f

typedef unsigned int       u32;
typedef unsigned long long u64;

// ---------------- scratch (device globals; no allocation allowed) ----------
__device__ float  g_Q[TT*ED];
__device__ u32    g_Kp[TT*512];            // fp16x2 K (rope applied), dim-pair packed
__device__ u32    g_Vp16[TT*512];          // fp16x2 V, dim-pair packed, row-major
__device__ float  g_A [TT*ED];
__device__ float2 g_cs[SEQL*16];           // rope cos/sin table [t][j]

// ---------------- helpers --------------------------------------------------
__device__ __forceinline__ void mma_fp16(float4& c, const u32* a, const u32* b) {
    asm volatile(
        "mma.sync.aligned.m16n8k16.row.col.f32.f16.f16.f32 "
        "{%0,%1,%2,%3},{%4,%5,%6,%7},{%8,%9},{%0,%1,%2,%3};"
        : "+f"(c.x), "+f"(c.y), "+f"(c.z), "+f"(c.w)
        : "r"(a[0]), "r"(a[1]), "r"(a[2]), "r"(a[3]), "r"(b[0]), "r"(b[1]));
}
// split float pair -> packed fp16x2 hi and lo (fp16 hi+lo ~ 22 mantissa bits)
__device__ __forceinline__ void split2h(float vx, float vy, u32& hi2, u32& lo2) {
    __half hx = __float2half_rn(vx);
    __half hy = __float2half_rn(vy);
    __half lx = __float2half_rn(vx - __half2float(hx));
    __half ly = __float2half_rn(vy - __half2float(hy));
    __half2 h2 = __halves2half2(hx, hy);
    __half2 l2 = __halves2half2(lx, ly);
    hi2 = *(u32*)&h2;
    lo2 = *(u32*)&l2;
}
__device__ __forceinline__ u32 pkh(float x, float y) {
    __half2 h = __floats2half2_rn(x, y);
    return *(u32*)&h;
}
__device__ __forceinline__ float ex2(float x) {
    float r; asm("ex2.approx.ftz.f32 %0, %1;" : "=f"(r) : "f"(x)); return r;
}
__device__ __forceinline__ void cpa16(u32 smem_addr, const void* gptr) {
    asm volatile("cp.async.cg.shared.global [%0], [%1], 16;"
                 :: "r"(smem_addr), "l"(gptr));
}
__device__ __forceinline__ void cpa_commit() {
    asm volatile("cp.async.commit_group;" ::: "memory");
}
__device__ __forceinline__ void cpa_wait0() {
    asm volatile("cp.async.wait_group 0;" ::: "memory");
}
#define LDSM4(r0,r1,r2,r3,addr) \
    asm volatile("ldmatrix.sync.aligned.m8n8.x4.shared.b16 {%0,%1,%2,%3},[%4];" \
                 : "=r"(r0),"=r"(r1),"=r"(r2),"=r"(r3) : "r"(addr))
#define LDSM4T(r0,r1,r2,r3,addr) \
    asm volatile("ldmatrix.sync.aligned.m8n8.x4.trans.shared.b16 {%0,%1,%2,%3},[%4];" \
                 : "=r"(r0),"=r"(r1),"=r"(r2),"=r"(r3) : "r"(addr))

// warp-collective lambda (lane-indexed; all 32 lanes participate)
__device__ __forceinline__ float calc_lam(
    const float* lq1, const float* lk1, const float* lq2, const float* lk2, int lane)
{
    float s1 = lq1[lane] * lk1[lane];
    float s2 = lq2[lane] * lk2[lane];
    #pragma unroll
    for (int o = 16; o; o >>= 1) {
        s1 += __shfl_xor_sync(0xffffffffu, s1, o);
        s2 += __shfl_xor_sync(0xffffffffu, s2, o);
    }
    return expf(s1) - expf(s2) + LAMBDA_INIT;
}

// ---------------- rope cos/sin table ----------------------------------------
__global__ void cs_kernel(float2* __restrict__ cs)
{
    int i = blockIdx.x * blockDim.x + threadIdx.x;
    if (i >= SEQL * 16) return;
    int t = i >> 4, j = i & 15;
    float ang = expf(-(float)j * (9.210340371976184f / 15.0f));
    float s, c;
    sincosf((float)t * ang, &s, &c);
    cs[i] = make_float2(c, s);
}

// ---------------- fused QKV GEMM (2-term split-fp16) ------------------------
// Epilogue: Q -> rope -> fp32; K -> rope -> fp16x2; V -> fp16x2 row-major.
__global__ void __launch_bounds__(256) gemm_qkv(
    const float* __restrict__ A, const float* __restrict__ Wq,
    const float* __restrict__ Wk, const float* __restrict__ Wv,
    const float2* __restrict__ cs,
    float* __restrict__ Qo, u32* __restrict__ Kpo, u32* __restrict__ Vpo)
{
    __shared__ u32 Ah[128][20];
    __shared__ u32 Al[128][20];
    __shared__ u32 Bh[64][20];

    const int tid    = threadIdx.x;
    const int warp   = tid >> 5;
    const int lane   = tid & 31;
    const int gid    = lane >> 2;
    const int tig    = lane & 3;
    const int warp_m = warp >> 1;
    const int warp_n = warp & 1;
    const int sel    = blockIdx.x >> 4;
    const int ntile  = blockIdx.x & 15;
    const int K      = ED;

    const float* W  = (sel == 0) ? Wq : (sel == 1) ? Wk : Wv;
    const float* Ab = A + (size_t)blockIdx.y * 128 * K;
    const float* Bb = W + (size_t)ntile * 64 * K;

    float4 cacc[2][4];
    #pragma unroll
    for (int i = 0; i < 2; i++)
        #pragma unroll
        for (int j = 0; j < 4; j++) cacc[i][j] = make_float4(0.f,0.f,0.f,0.f);

    for (int k0 = 0; k0 < K; k0 += 32) {
        #pragma unroll
        for (int i = 0; i < 4; i++) {
            int idx = tid + i*256;
            int r = idx >> 3, c = (idx & 7) << 2;
            float4 v = *(const float4*)(Ab + (size_t)r * K + k0 + c);
            split2h(v.x, v.y, Ah[r][(c>>1)  ], Al[r][(c>>1)  ]);
            split2h(v.z, v.w, Ah[r][(c>>1)+1], Al[r][(c>>1)+1]);
        }
        #pragma unroll
        for (int i = 0; i < 2; i++) {
            int idx = tid + i*256;
            int r = idx >> 3, c = (idx & 7) << 2;
            float4 v = *(const float4*)(Bb + (size_t)r * K + k0 + c);
            Bh[r][(c>>1)  ] = pkh(v.x, v.y);
            Bh[r][(c>>1)+1] = pkh(v.z, v.w);
        }
        __syncthreads();

        #pragma unroll
        for (int kt = 0; kt < 2; kt++) {
            const int cb = kt*8 + tig;
            u32 ah[2][4], al[2][4], bh[4][2];
            #pragma unroll
            for (int mt = 0; mt < 2; mt++) {
                int r0 = warp_m*32 + mt*16 + gid;
                ah[mt][0] = Ah[r0  ][cb];   al[mt][0] = Al[r0  ][cb];
                ah[mt][1] = Ah[r0+8][cb];   al[mt][1] = Al[r0+8][cb];
                ah[mt][2] = Ah[r0  ][cb+4]; al[mt][2] = Al[r0  ][cb+4];
                ah[mt][3] = Ah[r0+8][cb+4]; al[mt][3] = Al[r0+8][cb+4];
            }
            #pragma unroll
            for (int nt = 0; nt < 4; nt++) {
                int n = warp_n*32 + nt*8 + gid;
                bh[nt][0] = Bh[n][cb];
                bh[nt][1] = Bh[n][cb+4];
            }
            #pragma unroll
            for (int mt = 0; mt < 2; mt++)
                #pragma unroll
                for (int nt = 0; nt < 4; nt++) {
                    mma_fp16(cacc[mt][nt], ah[mt], bh[nt]);
                    mma_fp16(cacc[mt][nt], al[mt], bh[nt]);
                }
        }
        __syncthreads();
    }

    #pragma unroll
    for (int mt = 0; mt < 2; mt++) {
        #pragma unroll
        for (int nt = 0; nt < 4; nt++) {
            int row = blockIdx.y*128 + warp_m*32 + mt*16 + gid;
            int col = ntile*64 + warp_n*32 + nt*8 + tig*2;   // even
            float4 c = cacc[mt][nt];
            if (sel == 2) {
                Vpo[(size_t)row * 512 + (col >> 1)]     = pkh(c.x, c.y);
                Vpo[(size_t)(row+8) * 512 + (col >> 1)] = pkh(c.z, c.w);
            } else {
                int j  = (col & 31) >> 1;
                int t0 = row & (SEQL-1), t1 = (row+8) & (SEQL-1);
                float2 cs0 = cs[t0*16 + j];
                float2 cs1 = cs[t1*16 + j];
                float o1 = c.x*cs0.x - c.y*cs0.y, o2 = c.x*cs0.y + c.y*cs0.x;
                float p1 = c.z*cs1.x - c.w*cs1.y, p2 = c.z*cs1.y + c.w*cs1.x;
                if (sel == 0) {
                    *(float2*)(Qo + (size_t)row * ED + col)     = make_float2(o1, o2);
                    *(float2*)(Qo + (size_t)(row+8) * ED + col) = make_float2(p1, p2);
                } else {
                    Kpo[(size_t)row * 512 + (col >> 1)]     = pkh(o1, o2);
                    Kpo[(size_t)(row+8) * 512 + (col >> 1)] = pkh(p1, p2);
                }
            }
        }
    }
}

// ---------------- plain 2-term split-fp16 GEMM (for Wo) ---------------------
__global__ void __launch_bounds__(256) gemm_2xfp16(
    const float* __restrict__ A, const float* __restrict__ B,
    float* __restrict__ C, int M, int N, int K)
{
    __shared__ u32 Ah[128][20];
    __shared__ u32 Al[128][20];
    __shared__ u32 Bh[64][20];

    const int tid    = threadIdx.x;
    const int warp   = tid >> 5;
    const int lane   = tid & 31;
    const int gid    = lane >> 2;
    const int tig    = lane & 3;
    const int warp_m = warp >> 1;
    const int warp_n = warp & 1;

    const float* Ab = A + (size_t)blockIdx.y * 128 * K;
    const float* Bb = B + (size_t)blockIdx.x * 64  * K;

    float4 cacc[2][4];
    #pragma unroll
    for (int i = 0; i < 2; i++)
        #pragma unroll
        for (int j = 0; j < 4; j++) cacc[i][j] = make_float4(0.f,0.f,0.f,0.f);

    for (int k0 = 0; k0 < K; k0 += 32) {
        #pragma unroll
        for (int i = 0; i < 4; i++) {
            int idx = tid + i*256;
            int r = idx >> 3, c = (idx & 7) << 2;
            float4 v = *(const float4*)(Ab + (size_t)r * K + k0 + c);
            split2h(v.x, v.y, Ah[r][(c>>1)  ], Al[r][(c>>1)  ]);
            split2h(v.z, v.w, Ah[r][(c>>1)+1], Al[r][(c>>1)+1]);
        }
        #pragma unroll
        for (int i = 0; i < 2; i++) {
            int idx = tid + i*256;
            int r = idx >> 3, c = (idx & 7) << 2;
            float4 v = *(const float4*)(Bb + (size_t)r * K + k0 + c);
            Bh[r][(c>>1)  ] = pkh(v.x, v.y);
            Bh[r][(c>>1)+1] = pkh(v.z, v.w);
        }
        __syncthreads();

        #pragma unroll
        for (int kt = 0; kt < 2; kt++) {
            const int cb = kt*8 + tig;
            u32 ah[2][4], al[2][4], bh[4][2];
            #pragma unroll
            for (int mt = 0; mt < 2; mt++) {
                int r0 = warp_m*32 + mt*16 + gid;
                ah[mt][0] = Ah[r0  ][cb];   al[mt][0] = Al[r0  ][cb];
                ah[mt][1] = Ah[r0+8][cb];   al[mt][1] = Al[r0+8][cb];
                ah[mt][2] = Ah[r0  ][cb+4]; al[mt][2] = Al[r0  ][cb+4];
                ah[mt][3] = Ah[r0+8][cb+4]; al[mt][3] = Al[r0+8][cb+4];
            }
            #pragma unroll
            for (int nt = 0; nt < 4; nt++) {
                int n = warp_n*32 + nt*8 + gid;
                bh[nt][0] = Bh[n][cb];
                bh[nt][1] = Bh[n][cb+4];
            }
            #pragma unroll
            for (int mt = 0; mt < 2; mt++)
                #pragma unroll
                for (int nt = 0; nt < 4; nt++) {
                    mma_fp16(cacc[mt][nt], ah[mt], bh[nt]);
                    mma_fp16(cacc[mt][nt], al[mt], bh[nt]);
                }
        }
        __syncthreads();
    }

    #pragma unroll
    for (int mt = 0; mt < 2; mt++) {
        #pragma unroll
        for (int nt = 0; nt < 4; nt++) {
            int row = blockIdx.y*128 + warp_m*32 + mt*16 + gid;
            int col = blockIdx.x*64  + warp_n*32 + nt*8 + tig*2;
            float4 c = cacc[mt][nt];
            *(float2*)(C + (size_t)row * N + col)     = make_float2(c.x, c.y);
            *(float2*)(C + (size_t)(row+8) * N + col) = make_float2(c.z, c.w);
        }
    }
}

// ---------------- flash attention v10: dual-component + fused combine -------
// Each block handles BOTH components (hq=2h, 2h+1) of head h: shared V tile,
// two K tiles. Epilogue computes a = o1/l1 - lam*o2/l2, RMS-norms the 64-col
// row in registers (quad shfl), scales by rmsw*(1-LI), writes A directly.
#define KH_STRIDE 20
#define VT_STRIDE 36               /* u32 per V row (32 data + 4 pad) = 144 B */
#define KBUF (128*KH_STRIDE)       /* 2560 u32 */
#define VTBUF (128*VT_STRIDE)      /* 4608 u32 */

__global__ void __launch_bounds__(256, 1) flash_v10(
    const float* __restrict__ Q, const u32* __restrict__ Kpg,
    const u32* __restrict__ Vpg,
    const float* __restrict__ lq1, const float* __restrict__ lk1,
    const float* __restrict__ lq2, const float* __restrict__ lk2,
    const float* __restrict__ rmsw, float* __restrict__ Aout)
{
    extern __shared__ u32 sm[];
    u32* K0S = sm;                  // [2][KBUF]  comp0
    u32* K1S = K0S + 2*KBUF;        // [2][KBUF]  comp1
    u32* VtS = K1S + 2*KBUF;        // [2][VTBUF]

    const int tid  = threadIdx.x;
    const int warp = tid >> 5;
    const int lane = tid & 31;
    const int gid  = lane >> 2;
    const int tig  = lane & 3;
    const int bh   = blockIdx.y;
    const int b    = bh >> 4;
    const int h    = bh & 15;
    const int q0   = blockIdx.x * 128;
    const int r0   = warp * 16 + gid;
    const int r1   = r0 + 8;

    const u32* kb0 = Kpg + (size_t)(b * SEQL) * 512 + (2*h    ) * 16;
    const u32* kb1 = Kpg + (size_t)(b * SEQL) * 512 + (2*h + 1) * 16;
    const u32* vpb = Vpg + (size_t)(b * SEQL) * 512 + h * 32;

    const int kr  = tid >> 2;
    const int kd4 = (tid & 3) << 2;

    u32 k0A = (u32)__cvta_generic_to_shared(K0S);
    u32 k1A = (u32)__cvta_generic_to_shared(K1S);
    u32 vtA = (u32)__cvta_generic_to_shared(VtS);

    const int g8 = lane & 7, mm = lane >> 3;
    const u32 kfo  = (u32)((((mm>>1)*8 + g8)*KH_STRIDE + (mm&1)*4) * 4);
    const u32 vfoT = (u32)(((mm&1)*8 + g8)*144 + ((mm>>1)*16));

    // lambda (warp-collective, all lanes)
    const float lam = calc_lam(lq1, lk1, lq2, lk2, lane);

    // ---- prefetch tile 0 into buffer 0
    {
        #pragma unroll
        for (int i = 0; i < 2; i++) {
            int r = kr + i*64;
            cpa16(k0A + (r*KH_STRIDE + kd4)*4, kb0 + (size_t)r*512 + kd4);
            cpa16(k1A + (r*KH_STRIDE + kd4)*4, kb1 + (size_t)r*512 + kd4);
        }
        #pragma unroll
        for (int i = 0; i < 4; i++) {
            int idx = tid + i*256;
            int r = idx >> 3, q4 = (idx & 7) << 2;
            cpa16(vtA + (r*VT_STRIDE + q4)*4, vpb + (size_t)r*512 + q4);
        }
        cpa_commit();
    }

    // Q fragments hi/lo fp16 for both components, scale folded before split
    u32 aqh[2][2][4], aql[2][2][4];
    #pragma unroll
    for (int cpi = 0; cpi < 2; cpi++) {
        const float* qb = Q + (size_t)(b * SEQL + q0) * ED + (2*h + cpi) * 32;
        #pragma unroll
        for (int kt = 0; kt < 2; kt++) {
            int k0 = kt*16 + 2*tig;
            split2h(qb[(size_t)r0*ED + k0    ]*QSCL, qb[(size_t)r0*ED + k0 + 1]*QSCL, aqh[cpi][kt][0], aql[cpi][kt][0]);
            split2h(qb[(size_t)r1*ED + k0    ]*QSCL, qb[(size_t)r1*ED + k0 + 1]*QSCL, aqh[cpi][kt][1], aql[cpi][kt][1]);
            split2h(qb[(size_t)r0*ED + k0 + 8]*QSCL, qb[(size_t)r0*ED + k0 + 9]*QSCL, aqh[cpi][kt][2], aql[cpi][kt][2]);
            split2h(qb[(size_t)r1*ED + k0 + 8]*QSCL, qb[(size_t)r1*ED + k0 + 9]*QSCL, aqh[cpi][kt][3], aql[cpi][kt][3]);
        }
    }

    float4 oacc0[8], oacc1[8];
    #pragma unroll
    for (int i = 0; i < 8; i++) {
        oacc0[i] = make_float4(0.f,0.f,0.f,0.f);
        oacc1[i] = make_float4(0.f,0.f,0.f,0.f);
    }
    float l00 = 0.f, l01 = 0.f, l10 = 0.f, l11 = 0.f;

    #pragma unroll 1
    for (int t = 0; t < SEQL/128; t++) {
        const int cur = t & 1;
        cpa_wait0();
        __syncthreads();

        if (t + 1 < SEQL/128) {
            const int s0 = (t+1) * 128;
            const int nb = 1 - cur;
            #pragma unroll
            for (int i = 0; i < 2; i++) {
                int r = kr + i*64;
                cpa16(k0A + (nb*KBUF + r*KH_STRIDE + kd4)*4, kb0 + (size_t)(s0 + r)*512 + kd4);
                cpa16(k1A + (nb*KBUF + r*KH_STRIDE + kd4)*4, kb1 + (size_t)(s0 + r)*512 + kd4);
            }
            #pragma unroll
            for (int i = 0; i < 4; i++) {
                int idx = tid + i*256;
                int r = idx >> 3, q4 = (idx & 7) << 2;
                cpa16(vtA + (nb*VTBUF + r*VT_STRIDE + q4)*4, vpb + (size_t)(s0 + r)*512 + q4);
            }
            cpa_commit();
        } else {
            cpa_commit();
        }

        const u32 vtC = vtA + cur*VTBUF*4;

        #pragma unroll
        for (int cpi = 0; cpi < 2; cpi++) {
            const u32 khC = (cpi ? k1A : k0A) + cur*KBUF*4;
            float4* oacc = cpi ? oacc1 : oacc0;

            // S = Q*K^T (log2 domain): 2-term split-fp16
            float4 sacc[16];
            #pragma unroll
            for (int nt = 0; nt < 16; nt++) sacc[nt] = make_float4(0.f,0.f,0.f,0.f);
            #pragma unroll
            for (int kt = 0; kt < 2; kt++) {
                #pragma unroll
                for (int p = 0; p < 8; p++) {
                    u32 h0,h1,h2,h3;
                    LDSM4(h0,h1,h2,h3, khC + kfo + (u32)((p*16*KH_STRIDE + kt*8)*4));
                    { u32 bf[2] = {h0,h1};
                      mma_fp16(sacc[2*p],   aqh[cpi][kt], bf);
                      mma_fp16(sacc[2*p],   aql[cpi][kt], bf); }
                    { u32 bf[2] = {h2,h3};
                      mma_fp16(sacc[2*p+1], aqh[cpi][kt], bf);
                      mma_fp16(sacc[2*p+1], aql[cpi][kt], bf); }
                }
            }

            // P = exp2(S); l on FMA pipe; P*V fp16 with trans-V fragments
            float la = 0.f, lb = 0.f;
            #pragma unroll
            for (int kt = 0; kt < 8; kt++) {
                float px = ex2(sacc[2*kt].x),   py = ex2(sacc[2*kt].y);
                float pz = ex2(sacc[2*kt].z),   pw = ex2(sacc[2*kt].w);
                float qx = ex2(sacc[2*kt+1].x), qy = ex2(sacc[2*kt+1].y);
                float qz = ex2(sacc[2*kt+1].z), qw = ex2(sacc[2*kt+1].w);
                la += px + py + qx + qy;
                lb += pz + pw + qz + qw;
                u32 ap[4];
                ap[0] = pkh(px, py);
                ap[1] = pkh(pz, pw);
                ap[2] = pkh(qx, qy);
                ap[3] = pkh(qz, qw);
                #pragma unroll
                for (int p = 0; p < 4; p++) {
                    u32 v0,v1,v2,v3;
                    LDSM4T(v0,v1,v2,v3, vtC + vfoT + (u32)(kt*2304 + p*32));
                    { u32 bpf[2] = {v0,v1}; mma_fp16(oacc[2*p],   ap, bpf); }
                    { u32 bpf[2] = {v2,v3}; mma_fp16(oacc[2*p+1], ap, bpf); }
                }
            }
            if (cpi == 0) { l00 += la; l01 += lb; }
            else          { l10 += la; l11 += lb; }
        }
    }

    // quad reduction of row sums
    l00 += __shfl_xor_sync(0xffffffffu, l00, 1);
    l00 += __shfl_xor_sync(0xffffffffu, l00, 2);
    l01 += __shfl_xor_sync(0xffffffffu, l01, 1);
    l01 += __shfl_xor_sync(0xffffffffu, l01, 2);
    l10 += __shfl_xor_sync(0xffffffffu, l10, 1);
    l10 += __shfl_xor_sync(0xffffffffu, l10, 2);
    l11 += __shfl_xor_sync(0xffffffffu, l11, 1);
    l11 += __shfl_xor_sync(0xffffffffu, l11, 2);
    const float inv00 = 1.f / l00, inv01 = 1.f / l01;
    const float inv10 = 1.f / l10, inv11 = 1.f / l11;

    // combine + RMS in registers
    float ss0 = 0.f, ss1 = 0.f;
    #pragma unroll
    for (int nt = 0; nt < 8; nt++) {
        float4 a;
        a.x = oacc0[nt].x*inv00 - lam * (oacc1[nt].x*inv10);
        a.y = oacc0[nt].y*inv00 - lam * (oacc1[nt].y*inv10);
        a.z = oacc0[nt].z*inv01 - lam * (oacc1[nt].z*inv11);
        a.w = oacc0[nt].w*inv01 - lam * (oacc1[nt].w*inv11);
        oacc0[nt] = a;
        ss0 += a.x*a.x + a.y*a.y;
        ss1 += a.z*a.z + a.w*a.w;
    }
    ss0 += __shfl_xor_sync(0xffffffffu, ss0, 1);
    ss0 += __shfl_xor_sync(0xffffffffu, ss0, 2);
    ss1 += __shfl_xor_sync(0xffffffffu, ss1, 1);
    ss1 += __shfl_xor_sync(0xffffffffu, ss1, 2);
    const float rs0 = rsqrtf(ss0 * (1.0f/64.0f) + 1e-5f) * (1.0f - LAMBDA_INIT);
    const float rs1 = rsqrtf(ss1 * (1.0f/64.0f) + 1e-5f) * (1.0f - LAMBDA_INIT);

    float* outp = Aout + (size_t)(b * SEQL + q0) * ED + h * 64;
    #pragma unroll
    for (int nt = 0; nt < 8; nt++) {
        int col = nt*8 + 2*tig;
        float2 w = *(const float2*)(rmsw + col);
        float4 a = oacc0[nt];
        *(float2*)(outp + (size_t)r0*ED + col) = make_float2(a.x*rs0*w.x, a.y*rs0*w.y);
        *(float2*)(outp + (size_t)r1*ED + col) = make_float2(a.z*rs1*w.x, a.w*rs1*w.y);
    }
}

// ---------------- launch ---------------------------------------------------
extern "C" void kernel_launch(void* const* d_in, const int* in_sizes, int n_in,
                              void* d_out, int out_size)
{
    const float* x    = (const float*)d_in[0];
    const float* Wq   = (const float*)d_in[1];
    const float* Wk   = (const float*)d_in[2];
    const float* Wv   = (const float*)d_in[3];
    const float* Wo   = (const float*)d_in[4];
    const float* lq1  = (const float*)d_in[5];
    const float* lk1  = (const float*)d_in[6];
    const float* lq2  = (const float*)d_in[7];
    const float* lk2  = (const float*)d_in[8];
    const float* rmsw = (const float*)d_in[9];
    float* out = (float*)d_out;

    float *Q, *A;
    u32 *Kp, *Vp16;
    float2* cs;
    cudaGetSymbolAddress((void**)&Q,  g_Q);
    cudaGetSymbolAddress((void**)&A,  g_A);
    cudaGetSymbolAddress((void**)&Kp,   g_Kp);
    cudaGetSymbolAddress((void**)&Vp16, g_Vp16);
    cudaGetSymbolAddress((void**)&cs,   g_cs);

    const int flash_smem = (4*KBUF + 2*VTBUF) * 4;   // 77824 B
    cudaFuncSetAttribute(flash_v10, cudaFuncAttributeMaxDynamicSharedMemorySize, flash_smem);

    cs_kernel<<<(SEQL*16 + 255)/256, 256>>>(cs);

    gemm_qkv<<<dim3(48, TT/128), 256>>>(x, Wq, Wk, Wv, cs, Q, Kp, Vp16);

    flash_v10<<<dim3(SEQL/128, NB*16), 256, flash_smem>>>(
        Q, Kp, Vp16, lq1, lk1, lq2, lk2, rmsw, A);

    gemm_2xfp16<<<dim3(ED/64, TT/128), 256>>>(A, Wo, out, TT, ED, ED);
}

// round 17
// speedup vs baseline: 1.1909x; 1.1909x over previous
#include <cuda_runtime.h>
#include <cuda_bf16.h>
#include <cuda_fp16.h>
#include <math.h>

#define SEQL 2048
#define NB 2
#define TT (NB*SEQL)   /* 4096 tokens total */
#define ED 1024

#define LAMBDA_INIT 0.7836057665315f
/* QK_SCALE * log2(e) : scores computed directly in log2 domain */
#define QSCL 0.25503482f

typedef unsigned int       u32;
typedef unsigned long long u64;

// ---------------- scratch (device globals; no allocation allowed) ----------
__device__ float  g_Q[TT*ED];
__device__ u32    g_Kp[TT*512];            // fp16x2 K (rope applied), dim-pair packed
__device__ u32    g_Vp16[TT*512];          // fp16x2 V, dim-pair packed, row-major
__device__ float  g_A1[TT*ED];
__device__ float  g_A2[TT*ED];
__device__ u32    g_xh[TT*512];            // x split fp16 hi (pairs)
__device__ u32    g_xl[TT*512];            // x split fp16 lo
__device__ u32    g_Wh[4*1024*512];        // Wq/Wk/Wv/Wo single-rounded fp16 pairs
__device__ u32    g_Ah[TT*512];            // combined A split hi
__device__ u32    g_Al[TT*512];            // combined A split lo
__device__ float2 g_cs[SEQL*16];           // rope cos/sin table [t][j]

// ---------------- helpers --------------------------------------------------
__device__ __forceinline__ void mma_fp16(float4& c, const u32* a, const u32* b) {
    asm volatile(
        "mma.sync.aligned.m16n8k16.row.col.f32.f16.f16.f32 "
        "{%0,%1,%2,%3},{%4,%5,%6,%7},{%8,%9},{%0,%1,%2,%3};"
        : "+f"(c.x), "+f"(c.y), "+f"(c.z), "+f"(c.w)
        : "r"(a[0]), "r"(a[1]), "r"(a[2]), "r"(a[3]), "r"(b[0]), "r"(b[1]));
}
__device__ __forceinline__ void split2h(float vx, float vy, u32& hi2, u32& lo2) {
    __half hx = __float2half_rn(vx);
    __half hy = __float2half_rn(vy);
    __half lx = __float2half_rn(vx - __half2float(hx));
    __half ly = __float2half_rn(vy - __half2float(hy));
    __half2 h2 = __halves2half2(hx, hy);
    __half2 l2 = __halves2half2(lx, ly);
    hi2 = *(u32*)&h2;
    lo2 = *(u32*)&l2;
}
__device__ __forceinline__ u32 pkh(float x, float y) {
    __half2 h = __floats2half2_rn(x, y);
    return *(u32*)&h;
}
__device__ __forceinline__ float ex2(float x) {
    float r; asm("ex2.approx.ftz.f32 %0, %1;" : "=f"(r) : "f"(x)); return r;
}
__device__ __forceinline__ void cpa16(u32 smem_addr, const void* gptr) {
    asm volatile("cp.async.cg.shared.global [%0], [%1], 16;"
                 :: "r"(smem_addr), "l"(gptr));
}
__device__ __forceinline__ void cpa_commit() {
    asm volatile("cp.async.commit_group;" ::: "memory");
}
__device__ __forceinline__ void cpa_wait0() {
    asm volatile("cp.async.wait_group 0;" ::: "memory");
}
#define LDSM4(r0,r1,r2,r3,addr) \
    asm volatile("ldmatrix.sync.aligned.m8n8.x4.shared.b16 {%0,%1,%2,%3},[%4];" \
                 : "=r"(r0),"=r"(r1),"=r"(r2),"=r"(r3) : "r"(addr))
#define LDSM4T(r0,r1,r2,r3,addr) \
    asm volatile("ldmatrix.sync.aligned.m8n8.x4.trans.shared.b16 {%0,%1,%2,%3},[%4];" \
                 : "=r"(r0),"=r"(r1),"=r"(r2),"=r"(r3) : "r"(addr))

// warp-collective lambda
__device__ __forceinline__ float calc_lam(
    const float* lq1, const float* lk1, const float* lq2, const float* lk2, int lane)
{
    float s1 = lq1[lane] * lk1[lane];
    float s2 = lq2[lane] * lk2[lane];
    #pragma unroll
    for (int o = 16; o; o >>= 1) {
        s1 += __shfl_xor_sync(0xffffffffu, s1, o);
        s2 += __shfl_xor_sync(0xffffffffu, s2, o);
    }
    return expf(s1) - expf(s2) + LAMBDA_INIT;
}

// ---------------- rope cos/sin table ----------------------------------------
__global__ void cs_kernel(float2* __restrict__ cs)
{
    int i = blockIdx.x * blockDim.x + threadIdx.x;
    if (i >= SEQL * 16) return;
    int t = i >> 4, j = i & 15;
    float ang = expf(-(float)j * (9.210340371976184f / 15.0f));
    float s, c;
    sincosf((float)t * ang, &s, &c);
    cs[i] = make_float2(c, s);
}

// ---------------- pre-split / pack kernels ----------------------------------
__global__ void splitX_kernel(const float* __restrict__ X,
                              u32* __restrict__ Xh, u32* __restrict__ Xl)
{
    int idx = blockIdx.x * blockDim.x + threadIdx.x;
    if (idx >= TT * 512) return;
    float2 v = *(const float2*)(X + 2 * (size_t)idx);
    split2h(v.x, v.y, Xh[idx], Xl[idx]);
}
__global__ void packW_kernel(const float* __restrict__ Wq, const float* __restrict__ Wk,
                             const float* __restrict__ Wv, const float* __restrict__ Wo,
                             u32* __restrict__ Wh)
{
    int idx = blockIdx.x * blockDim.x + threadIdx.x;   // over 1024*512
    if (idx >= 1024 * 512) return;
    int sel = blockIdx.y;
    const float* W = (sel == 0) ? Wq : (sel == 1) ? Wk : (sel == 2) ? Wv : Wo;
    float2 v = *(const float2*)(W + 2 * (size_t)idx);
    Wh[(size_t)sel * (1024*512) + idx] = pkh(v.x, v.y);
}

// ---------------- GEMM core (cp.async + ldmatrix, 2-term fp16) --------------
// SMEM layout (u32): Ah[2][2560], Al[2][2560], Bh[2][1280]; stride 20/row.
#define ASTG 2560
#define BSTG 1280
#define GEMM_SMEM ((2*ASTG*2 + 2*BSTG)*4)

__device__ __forceinline__ void gemm_prefetch(
    int tid, int st, int kc, int mrow, int nrow,
    u32 ahA, u32 alA, u32 bhA,
    const u32* __restrict__ Ahg, const u32* __restrict__ Alg,
    const u32* __restrict__ Bhg)
{
    #pragma unroll
    for (int i = 0; i < 4; i++) {
        int idx = tid + i*256;
        int arr = idx >> 9, r = (idx >> 2) & 127, c4 = (idx & 3) << 2;
        u32 dst = (arr ? alA : ahA) + ((u32)st*ASTG + r*20 + c4)*4;
        const u32* src = (arr ? Alg : Ahg) + (size_t)(mrow + r)*512 + kc*16 + c4;
        cpa16(dst, src);
    }
    {
        int r = tid >> 2, c4 = (tid & 3) << 2;
        cpa16(bhA + ((u32)st*BSTG + r*20 + c4)*4,
              Bhg + (size_t)(nrow + r)*512 + kc*16 + c4);
    }
}

// mainloop body shared by both GEMMs (expands inline)
__device__ __forceinline__ void gemm_mainloop(
    int tid, int mrow, int nrow,
    u32 ahA, u32 alA, u32 bhA, u32 afo, u32 bfo,
    int warp_m, int warp_n,
    const u32* __restrict__ Ahg, const u32* __restrict__ Alg,
    const u32* __restrict__ Bhg, float4 cacc[2][4])
{
    gemm_prefetch(tid, 0, 0, mrow, nrow, ahA, alA, bhA, Ahg, Alg, Bhg);
    cpa_commit();

    #pragma unroll 1
    for (int kc = 0; kc < 32; kc++) {
        const int cur = kc & 1;
        cpa_wait0();
        __syncthreads();
        if (kc + 1 < 32)
            gemm_prefetch(tid, 1 - cur, kc + 1, mrow, nrow, ahA, alA, bhA, Ahg, Alg, Bhg);
        cpa_commit();

        const u32 ahC = ahA + cur*ASTG*4;
        const u32 alC = alA + cur*ASTG*4;
        const u32 bhC = bhA + cur*BSTG*4;

        #pragma unroll
        for (int kt = 0; kt < 2; kt++) {
            u32 ah[2][4], al[2][4], bh[4][2];
            #pragma unroll
            for (int mt = 0; mt < 2; mt++) {
                u32 base = (u32)((((warp_m*32 + mt*16)*20) + kt*8) * 4);
                LDSM4(ah[mt][0], ah[mt][1], ah[mt][2], ah[mt][3], ahC + base + afo);
                LDSM4(al[mt][0], al[mt][1], al[mt][2], al[mt][3], alC + base + afo);
            }
            #pragma unroll
            for (int p = 0; p < 2; p++) {
                u32 base = (u32)((((warp_n*32 + p*16)*20) + kt*8) * 4);
                u32 h0,h1,h2,h3;
                LDSM4(h0,h1,h2,h3, bhC + base + bfo);
                bh[2*p][0] = h0;   bh[2*p][1] = h1;
                bh[2*p+1][0] = h2; bh[2*p+1][1] = h3;
            }
            #pragma unroll
            for (int mt = 0; mt < 2; mt++)
                #pragma unroll
                for (int nt = 0; nt < 4; nt++) {
                    mma_fp16(cacc[mt][nt], ah[mt], bh[nt]);
                    mma_fp16(cacc[mt][nt], al[mt], bh[nt]);
                }
        }
    }
}

// ---------------- fused QKV GEMM (pre-split operands) ------------------------
__global__ void __launch_bounds__(256) gemm_qkv(
    const u32* __restrict__ Ahg, const u32* __restrict__ Alg,
    const u32* __restrict__ Whg, const float2* __restrict__ cs,
    float* __restrict__ Qo, u32* __restrict__ Kpo, u32* __restrict__ Vpo)
{
    extern __shared__ u32 sm[];
    const int tid    = threadIdx.x;
    const int warp   = tid >> 5;
    const int lane   = tid & 31;
    const int gid    = lane >> 2;
    const int tig    = lane & 3;
    const int warp_m = warp >> 1;
    const int warp_n = warp & 1;
    const int sel    = blockIdx.x >> 4;
    const int ntile  = blockIdx.x & 15;
    const int mrow   = blockIdx.y * 128;
    const int nrow   = ntile * 64;

    const u32* Bhg = Whg + (size_t)sel * (1024*512);

    u32 ahA = (u32)__cvta_generic_to_shared(sm);
    u32 alA = ahA + 2*ASTG*4;
    u32 bhA = alA + 2*ASTG*4;

    const int g8 = lane & 7, mm = lane >> 3;
    const u32 afo = (u32)(((((mm&1)*8 + g8)*20) + (mm>>1)*4) * 4);
    const u32 bfo = (u32)(((((mm>>1)*8 + g8)*20) + (mm&1)*4) * 4);

    float4 cacc[2][4];
    #pragma unroll
    for (int i = 0; i < 2; i++)
        #pragma unroll
        for (int j = 0; j < 4; j++) cacc[i][j] = make_float4(0.f,0.f,0.f,0.f);

    gemm_mainloop(tid, mrow, nrow, ahA, alA, bhA, afo, bfo,
                  warp_m, warp_n, Ahg, Alg, Bhg, cacc);

    #pragma unroll
    for (int mt = 0; mt < 2; mt++) {
        #pragma unroll
        for (int nt = 0; nt < 4; nt++) {
            int row = mrow + warp_m*32 + mt*16 + gid;
            int col = nrow + warp_n*32 + nt*8 + tig*2;   // even
            float4 c = cacc[mt][nt];
            if (sel == 2) {
                Vpo[(size_t)row * 512 + (col >> 1)]     = pkh(c.x, c.y);
                Vpo[(size_t)(row+8) * 512 + (col >> 1)] = pkh(c.z, c.w);
            } else {
                int j  = (col & 31) >> 1;
                int t0 = row & (SEQL-1), t1 = (row+8) & (SEQL-1);
                float2 cs0 = cs[t0*16 + j];
                float2 cs1 = cs[t1*16 + j];
                float o1 = c.x*cs0.x - c.y*cs0.y, o2 = c.x*cs0.y + c.y*cs0.x;
                float p1 = c.z*cs1.x - c.w*cs1.y, p2 = c.z*cs1.y + c.w*cs1.x;
                if (sel == 0) {
                    *(float2*)(Qo + (size_t)row * ED + col)     = make_float2(o1, o2);
                    *(float2*)(Qo + (size_t)(row+8) * ED + col) = make_float2(p1, p2);
                } else {
                    Kpo[(size_t)row * 512 + (col >> 1)]     = pkh(o1, o2);
                    Kpo[(size_t)(row+8) * 512 + (col >> 1)] = pkh(p1, p2);
                }
            }
        }
    }
}

// ---------------- Wo GEMM (pre-split A, fp32 out) ----------------------------
__global__ void __launch_bounds__(256) gemm_wo(
    const u32* __restrict__ Ahg, const u32* __restrict__ Alg,
    const u32* __restrict__ Bhg, float* __restrict__ C)
{
    extern __shared__ u32 sm[];
    const int tid    = threadIdx.x;
    const int warp   = tid >> 5;
    const int lane   = tid & 31;
    const int gid    = lane >> 2;
    const int tig    = lane & 3;
    const int warp_m = warp >> 1;
    const int warp_n = warp & 1;
    const int mrow   = blockIdx.y * 128;
    const int nrow   = blockIdx.x * 64;

    u32 ahA = (u32)__cvta_generic_to_shared(sm);
    u32 alA = ahA + 2*ASTG*4;
    u32 bhA = alA + 2*ASTG*4;

    const int g8 = lane & 7, mm = lane >> 3;
    const u32 afo = (u32)(((((mm&1)*8 + g8)*20) + (mm>>1)*4) * 4);
    const u32 bfo = (u32)(((((mm>>1)*8 + g8)*20) + (mm&1)*4) * 4);

    float4 cacc[2][4];
    #pragma unroll
    for (int i = 0; i < 2; i++)
        #pragma unroll
        for (int j = 0; j < 4; j++) cacc[i][j] = make_float4(0.f,0.f,0.f,0.f);

    gemm_mainloop(tid, mrow, nrow, ahA, alA, bhA, afo, bfo,
                  warp_m, warp_n, Ahg, Alg, Bhg, cacc);

    #pragma unroll
    for (int mt = 0; mt < 2; mt++) {
        #pragma unroll
        for (int nt = 0; nt < 4; nt++) {
            int row = mrow + warp_m*32 + mt*16 + gid;
            int col = nrow + warp_n*32 + nt*8 + tig*2;
            float4 c = cacc[mt][nt];
            *(float2*)(C + (size_t)row * ED + col)     = make_float2(c.x, c.y);
            *(float2*)(C + (size_t)(row+8) * ED + col) = make_float2(c.z, c.w);
        }
    }
}

// ---------------- flash attention v9 (R14, unchanged) ------------------------
#define KH_STRIDE 20
#define VT_STRIDE 36               /* u32 per V row (32 data + 4 pad) = 144 B */
#define KBUF (128*KH_STRIDE)
#define VTBUF (128*VT_STRIDE)

__global__ void __launch_bounds__(256) flash_v9(
    const float* __restrict__ Q, const u32* __restrict__ Kpg,
    const u32* __restrict__ Vpg,
    float* __restrict__ A1, float* __restrict__ A2)
{
    extern __shared__ u32 sm[];
    u32* KhS = sm;
    u32* VtS = KhS + 2*KBUF;

    const int tid  = threadIdx.x;
    const int warp = tid >> 5;
    const int lane = tid & 31;
    const int gid  = lane >> 2;
    const int tig  = lane & 3;
    const int bh   = blockIdx.y;
    const int b    = bh >> 5;
    const int hq   = bh & 31;
    const int h    = hq >> 1;
    const int comp = hq & 1;
    const int q0   = blockIdx.x * 128;
    const int r0   = warp * 16 + gid;
    const int r1   = r0 + 8;

    const u32* khb = Kpg + (size_t)(b * SEQL) * 512 + hq * 16;
    const u32* vpb = Vpg + (size_t)(b * SEQL) * 512 + h * 32;

    const int kr  = tid >> 2;
    const int kd4 = (tid & 3) << 2;

    u32 khA = (u32)__cvta_generic_to_shared(KhS);
    u32 vtA = (u32)__cvta_generic_to_shared(VtS);

    const int g8 = lane & 7, mm = lane >> 3;
    const u32 kfo  = (u32)((((mm>>1)*8 + g8)*KH_STRIDE + (mm&1)*4) * 4);
    const u32 vfoT = (u32)(((mm&1)*8 + g8)*144 + ((mm>>1)*16));

    {
        #pragma unroll
        for (int i = 0; i < 2; i++) {
            int r = kr + i*64;
            cpa16(khA + (r*KH_STRIDE + kd4)*4, khb + (size_t)r*512 + kd4);
        }
        #pragma unroll
        for (int i = 0; i < 4; i++) {
            int idx = tid + i*256;
            int r = idx >> 3, q4 = (idx & 7) << 2;
            cpa16(vtA + (r*VT_STRIDE + q4)*4, vpb + (size_t)r*512 + q4);
        }
        cpa_commit();
    }

    const float* qb = Q + (size_t)(b * SEQL + q0) * ED + hq * 32;
    u32 aqh[2][4], aql[2][4];
    #pragma unroll
    for (int kt = 0; kt < 2; kt++) {
        int k0 = kt*16 + 2*tig;
        split2h(qb[(size_t)r0*ED + k0    ]*QSCL, qb[(size_t)r0*ED + k0 + 1]*QSCL, aqh[kt][0], aql[kt][0]);
        split2h(qb[(size_t)r1*ED + k0    ]*QSCL, qb[(size_t)r1*ED + k0 + 1]*QSCL, aqh[kt][1], aql[kt][1]);
        split2h(qb[(size_t)r0*ED + k0 + 8]*QSCL, qb[(size_t)r0*ED + k0 + 9]*QSCL, aqh[kt][2], aql[kt][2]);
        split2h(qb[(size_t)r1*ED + k0 + 8]*QSCL, qb[(size_t)r1*ED + k0 + 9]*QSCL, aqh[kt][3], aql[kt][3]);
    }

    float4 oacc[8];
    #pragma unroll
    for (int i = 0; i < 8; i++) oacc[i] = make_float4(0.f,0.f,0.f,0.f);
    float l0 = 0.f, l1 = 0.f;

    #pragma unroll 1
    for (int t = 0; t < SEQL/128; t++) {
        const int cur = t & 1;
        cpa_wait0();
        __syncthreads();

        if (t + 1 < SEQL/128) {
            const int s0 = (t+1) * 128;
            const int nb = 1 - cur;
            #pragma unroll
            for (int i = 0; i < 2; i++) {
                int r = kr + i*64;
                cpa16(khA + (nb*KBUF + r*KH_STRIDE + kd4)*4, khb + (size_t)(s0 + r)*512 + kd4);
            }
            #pragma unroll
            for (int i = 0; i < 4; i++) {
                int idx = tid + i*256;
                int r = idx >> 3, q4 = (idx & 7) << 2;
                cpa16(vtA + (nb*VTBUF + r*VT_STRIDE + q4)*4, vpb + (size_t)(s0 + r)*512 + q4);
            }
            cpa_commit();
        } else {
            cpa_commit();
        }

        const u32 khC = khA + cur*KBUF*4;
        const u32 vtC = vtA + cur*VTBUF*4;

        float4 sacc[16];
        #pragma unroll
        for (int nt = 0; nt < 16; nt++) sacc[nt] = make_float4(0.f,0.f,0.f,0.f);
        #pragma unroll
        for (int kt = 0; kt < 2; kt++) {
            #pragma unroll
            for (int p = 0; p < 8; p++) {
                u32 h0,h1,h2,h3;
                LDSM4(h0,h1,h2,h3, khC + kfo + (u32)((p*16*KH_STRIDE + kt*8)*4));
                { u32 bf[2] = {h0,h1};
                  mma_fp16(sacc[2*p],   aqh[kt], bf);
                  mma_fp16(sacc[2*p],   aql[kt], bf); }
                { u32 bf[2] = {h2,h3};
                  mma_fp16(sacc[2*p+1], aqh[kt], bf);
                  mma_fp16(sacc[2*p+1], aql[kt], bf); }
            }
        }

        #pragma unroll
        for (int kt = 0; kt < 8; kt++) {
            float px = ex2(sacc[2*kt].x),   py = ex2(sacc[2*kt].y);
            float pz = ex2(sacc[2*kt].z),   pw = ex2(sacc[2*kt].w);
            float qx = ex2(sacc[2*kt+1].x), qy = ex2(sacc[2*kt+1].y);
            float qz = ex2(sacc[2*kt+1].z), qw = ex2(sacc[2*kt+1].w);
            l0 += px + py + qx + qy;
            l1 += pz + pw + qz + qw;
            u32 ap[4];
            ap[0] = pkh(px, py);
            ap[1] = pkh(pz, pw);
            ap[2] = pkh(qx, qy);
            ap[3] = pkh(qz, qw);
            #pragma unroll
            for (int p = 0; p < 4; p++) {
                u32 v0,v1,v2,v3;
                LDSM4T(v0,v1,v2,v3, vtC + vfoT + (u32)(kt*2304 + p*32));
                { u32 bpf[2] = {v0,v1}; mma_fp16(oacc[2*p],   ap, bpf); }
                { u32 bpf[2] = {v2,v3}; mma_fp16(oacc[2*p+1], ap, bpf); }
            }
        }
    }

    l0 += __shfl_xor_sync(0xffffffffu, l0, 1);
    l0 += __shfl_xor_sync(0xffffffffu, l0, 2);
    l1 += __shfl_xor_sync(0xffffffffu, l1, 1);
    l1 += __shfl_xor_sync(0xffffffffu, l1, 2);
    float inv0 = 1.f / l0, inv1 = 1.f / l1;

    float* outp = (comp ? A2 : A1) + (size_t)(b * SEQL + q0) * ED + h * 64;
    #pragma unroll
    for (int nt = 0; nt < 8; nt++) {
        int col = nt*8 + 2*tig;
        *(float2*)(outp + (size_t)r0*ED + col) = make_float2(oacc[nt].x*inv0, oacc[nt].y*inv0);
        *(float2*)(outp + (size_t)r1*ED + col) = make_float2(oacc[nt].z*inv1, oacc[nt].w*inv1);
    }
}

// ---------------- combine + RMS; writes A as split fp16 hi/lo ---------------
__global__ void __launch_bounds__(256) combine_rms(
    const float* __restrict__ A1n, const float* __restrict__ A2n,
    const float* __restrict__ lq1, const float* __restrict__ lk1,
    const float* __restrict__ lq2, const float* __restrict__ lk2,
    const float* __restrict__ rms_w, u32* __restrict__ Ahg, u32* __restrict__ Alg)
{
    int gw = (blockIdx.x * 256 + threadIdx.x) >> 5;   // (token,head)
    int lane = threadIdx.x & 31;
    if (gw >= TT * 16) return;
    float lam = calc_lam(lq1, lk1, lq2, lk2, lane);
    size_t base = (size_t)gw * 64;
    float2 v1 = *(const float2*)(A1n + base + 2*lane);
    float2 v2 = *(const float2*)(A2n + base + 2*lane);
    float a0 = v1.x - lam * v2.x;
    float a1 = v1.y - lam * v2.y;
    float ss = a0*a0 + a1*a1;
    #pragma unroll
    for (int o = 16; o; o >>= 1) ss += __shfl_xor_sync(0xffffffffu, ss, o);
    float r = rsqrtf(ss * (1.0f/64.0f) + 1e-5f) * (1.0f - LAMBDA_INIT);
    int tok = gw >> 4, h = gw & 15;
    u32 hi, lo;
    split2h(a0 * r * rms_w[2*lane], a1 * r * rms_w[2*lane + 1], hi, lo);
    Ahg[(size_t)tok * 512 + h*32 + lane] = hi;
    Alg[(size_t)tok * 512 + h*32 + lane] = lo;
}

// ---------------- launch ---------------------------------------------------
extern "C" void kernel_launch(void* const* d_in, const int* in_sizes, int n_in,
                              void* d_out, int out_size)
{
    const float* x    = (const float*)d_in[0];
    const float* Wq   = (const float*)d_in[1];
    const float* Wk   = (const float*)d_in[2];
    const float* Wv   = (const float*)d_in[3];
    const float* Wo   = (const float*)d_in[4];
    const float* lq1  = (const float*)d_in[5];
    const float* lk1  = (const float*)d_in[6];
    const float* lq2  = (const float*)d_in[7];
    const float* lk2  = (const float*)d_in[8];
    const float* rmsw = (const float*)d_in[9];
    float* out = (float*)d_out;

    float *Q, *A1, *A2;
    u32 *Kp, *Vp16, *xh, *xl, *Wh, *Ah, *Al;
    float2* cs;
    cudaGetSymbolAddress((void**)&Q,  g_Q);
    cudaGetSymbolAddress((void**)&A1, g_A1);
    cudaGetSymbolAddress((void**)&A2, g_A2);
    cudaGetSymbolAddress((void**)&Kp,   g_Kp);
    cudaGetSymbolAddress((void**)&Vp16, g_Vp16);
    cudaGetSymbolAddress((void**)&xh,  g_xh);
    cudaGetSymbolAddress((void**)&xl,  g_xl);
    cudaGetSymbolAddress((void**)&Wh,  g_Wh);
    cudaGetSymbolAddress((void**)&Ah,  g_Ah);
    cudaGetSymbolAddress((void**)&Al,  g_Al);
    cudaGetSymbolAddress((void**)&cs,  g_cs);

    const int flash_smem = (2*KBUF + 2*VTBUF) * 4;   // 57344 B
    cudaFuncSetAttribute(flash_v9, cudaFuncAttributeMaxDynamicSharedMemorySize, flash_smem);
    cudaFuncSetAttribute(gemm_qkv, cudaFuncAttributeMaxDynamicSharedMemorySize, GEMM_SMEM);
    cudaFuncSetAttribute(gemm_wo,  cudaFuncAttributeMaxDynamicSharedMemorySize, GEMM_SMEM);

    cs_kernel<<<(SEQL*16 + 255)/256, 256>>>(cs);
    splitX_kernel<<<(TT*512 + 255)/256, 256>>>(x, xh, xl);
    packW_kernel<<<dim3((1024*512 + 255)/256, 4), 256>>>(Wq, Wk, Wv, Wo, Wh);

    gemm_qkv<<<dim3(48, TT/128), 256, GEMM_SMEM>>>(xh, xl, Wh, cs, Q, Kp, Vp16);

    flash_v9<<<dim3(SEQL/128, NB*32), 256, flash_smem>>>(Q, Kp, Vp16, A1, A2);

    combine_rms<<<(TT*16)/8, 256>>>(A1, A2, lq1, lk1, lq2, lk2, rmsw, Ah, Al);

    gemm_wo<<<dim3(ED/64, TT/128), 256, GEMM_SMEM>>>(Ah, Al, Wh + 3*(1024*512), out);
}